// round 10
// baseline (speedup 1.0000x reference)
#include <cuda_runtime.h>

#define NS   16
#define NP   2048
#define DIMS 64
#define KK   16
#define QT   64      // queries per block
#define TJ   64      // candidate tile size
#define BLK  128
#define TOT  (NS*NP*KK)

typedef unsigned long long u64;
typedef unsigned int       u32;

__device__ float g_x2[NS * NP];

// ---------- row squared norms ----------
__global__ void x2_kernel(const float* __restrict__ h) {
    int r = blockIdx.x * blockDim.x + threadIdx.x;
    if (r >= NS * NP) return;
    const float4* p = (const float4*)(h + (size_t)r * DIMS);
    float s = 0.f;
#pragma unroll
    for (int t = 0; t < DIMS / 4; t++) {
        float4 v = p[t];
        s += v.x * v.x + v.y * v.y + v.z * v.z + v.w * v.w;
    }
    g_x2[r] = s;
}

// ---------- packed f32x2 helpers ----------
__device__ __forceinline__ u64 pack2(float x) {
    u64 r;
    asm("mov.b64 %0, {%1, %1};" : "=l"(r) : "f"(x));
    return r;
}
__device__ __forceinline__ void ffma2(u64& d, u64 a, u64 b) {
    asm("fma.rn.f32x2 %0, %1, %2, %0;" : "+l"(d) : "l"(a), "l"(b));
}
__device__ __forceinline__ float2 unpack2(u64 v) {
    float2 f;
    asm("mov.b64 {%0, %1}, %2;" : "=f"(f.x), "=f"(f.y) : "l"(v));
    return f;
}

// ---------- order-preserving float<->uint ----------
__device__ __forceinline__ u32 fkey(float f) {
    u32 u = __float_as_uint(f);
    return u ^ (u32)(((int)u >> 31) | 0x80000000);
}
__device__ __forceinline__ float funkey(u32 k) {
    u32 u = (k & 0x80000000u) ? (k ^ 0x80000000u) : ~k;
    return __uint_as_float(u);
}

// ---------- sorted register top-K (stable, strict <) ----------
__device__ __forceinline__ void topk_insert(float (&kd)[KK], int (&ki)[KK],
                                            float d, int j) {
    kd[KK - 1] = d;
    ki[KK - 1] = j;
#pragma unroll
    for (int t = KK - 1; t > 0; t--) {
        if (kd[t] < kd[t - 1]) {
            float td = kd[t]; kd[t] = kd[t - 1]; kd[t - 1] = td;
            int   ti = ki[t]; ki[t] = ki[t - 1]; ki[t - 1] = ti;
        }
    }
}

// shared layout (union):
//   phase 1: qsh[64][QT] (16KB) | csh[64][TJ] (16KB) | x2c[TJ] (256B)
//   phase 2: scratch[QT][4][KK] u64 (32KB)
#define SMEM_BYTES (DIMS*QT*4 + DIMS*TJ*4 + TJ*4)

__global__ __launch_bounds__(BLK, 4) void knn_kernel(const float* __restrict__ h,
                                                     float* __restrict__ out) {
    __shared__ __align__(16) char smem_raw[SMEM_BYTES];
    float (*qsh)[QT] = (float (*)[QT])smem_raw;
    float (*csh)[TJ] = (float (*)[TJ])(smem_raw + DIMS * QT * 4);
    float* x2c       = (float*)(smem_raw + DIMS * QT * 4 + DIMS * TJ * 4);

    const int b    = blockIdx.y;
    const int qt   = blockIdx.x;
    const int tid  = threadIdx.x;
    const int wid  = tid >> 5;
    const int lane = tid & 31;

    const int trow  = tid >> 1;      // staging row (0..63)
    const int thalf = tid & 1;       // staging d-half

    // stage query tile transposed: qsh[d][q]
    {
        const float4* src = (const float4*)(h + ((size_t)b * NP + qt * QT + trow) * DIMS
                                            + thalf * 32);
#pragma unroll
        for (int v = 0; v < 8; v++) {
            float4 f = src[v];
            int d = thalf * 32 + v * 4;
            qsh[d + 0][trow] = f.x;
            qsh[d + 1][trow] = f.y;
            qsh[d + 2][trow] = f.z;
            qsh[d + 3][trow] = f.w;
        }
    }

    // this thread's two queries (block-local 2*lane, 2*lane+1; same for all warps)
    const int qa_l = 2 * lane, qb_l = 2 * lane + 1;
    const float qx2a = g_x2[b * NP + qt * QT + qa_l];
    const float qx2b = g_x2[b * NP + qt * QT + qb_l];

    float kdA[KK], kdB[KK];
    int   kiA[KK], kiB[KK];
#pragma unroll
    for (int k = 0; k < KK; k++) {
        kdA[k] = __int_as_float(0x7f800000); kiA[k] = 0;
        kdB[k] = __int_as_float(0x7f800000); kiB[k] = 0;
    }

    const int js = wid * 16;   // each warp takes a fixed 16-cand slice of every tile

#pragma unroll 1
    for (int j0 = 0; j0 < NP; j0 += TJ) {
        __syncthreads();
        // stage candidate tile transposed: csh[d][j]
        {
            const float4* src = (const float4*)(h + ((size_t)b * NP + j0 + trow) * DIMS
                                                + thalf * 32);
#pragma unroll
            for (int v = 0; v < 8; v++) {
                float4 f = src[v];
                int d = thalf * 32 + v * 4;
                csh[d + 0][trow] = f.x;
                csh[d + 1][trow] = f.y;
                csh[d + 2][trow] = f.z;
                csh[d + 3][trow] = f.w;
            }
            if (tid < TJ) x2c[tid] = g_x2[b * NP + j0 + tid];
        }
        __syncthreads();

        u64 accA[8], accB[8];
#pragma unroll
        for (int p = 0; p < 8; p++) { accA[p] = 0ull; accB[p] = 0ull; }

#pragma unroll 16
        for (int d = 0; d < DIMS; d++) {
            float2 qf = *(const float2*)&qsh[d][qa_l];   // LDS.64, conflict-free
            u64 qpa = pack2(qf.x);
            u64 qpb = pack2(qf.y);
            const ulonglong2* srow = (const ulonglong2*)&csh[d][js];
#pragma unroll
            for (int p = 0; p < 4; p++) {
                ulonglong2 sv = srow[p];                 // broadcast LDS.128
                ffma2(accA[2 * p + 0], qpa, sv.x);
                ffma2(accA[2 * p + 1], qpa, sv.y);
                ffma2(accB[2 * p + 0], qpb, sv.x);
                ffma2(accB[2 * p + 1], qpb, sv.y);
            }
        }

#pragma unroll
        for (int p = 0; p < 8; p++) {
            float2 da = unpack2(accA[p]);
            float2 db = unpack2(accB[p]);
            int    j  = j0 + js + 2 * p;
            float  s0 = x2c[js + 2 * p + 0];
            float  s1 = x2c[js + 2 * p + 1];
            float a0 = fmaf(-2.f, da.x, qx2a + s0);
            float a1 = fmaf(-2.f, da.y, qx2a + s1);
            float b0 = fmaf(-2.f, db.x, qx2b + s0);
            float b1 = fmaf(-2.f, db.y, qx2b + s1);
            if (a0 < kdA[KK - 1]) topk_insert(kdA, kiA, a0, j);
            if (a1 < kdA[KK - 1]) topk_insert(kdA, kiA, a1, j + 1);
            if (b0 < kdB[KK - 1]) topk_insert(kdB, kiB, b0, j);
            if (b1 < kdB[KK - 1]) topk_insert(kdB, kiB, b1, j + 1);
        }
    }

    // ---- in-block merge of the 4 per-warp partial top-Ks ----
    __syncthreads();
    u64* sc = (u64*)smem_raw;    // scratch[QT][4][KK]
#pragma unroll
    for (int k = 0; k < KK; k++) {
        sc[((size_t)qa_l * 4 + wid) * KK + k] = ((u64)fkey(kdA[k]) << 32) | (u32)kiA[k];
        sc[((size_t)qb_l * 4 + wid) * KK + k] = ((u64)fkey(kdB[k]) << 32) | (u32)kiB[k];
    }
    __syncthreads();

    if (tid < QT) {
        const u64* L = sc + (size_t)tid * 4 * KK;
        u64 head[4];
        int ptr[4];
#pragma unroll
        for (int l = 0; l < 4; l++) { head[l] = L[l * KK]; ptr[l] = 0; }

        const int    gi   = b * NP + qt * QT + tid;
        const size_t base = (size_t)gi * KK;
        const float  goff = (float)(b * NP);
        const float  srcv = (float)(qt * QT + tid) + goff;

#pragma unroll
        for (int k = 0; k < KK; k++) {
            int best = 0;
#pragma unroll
            for (int l = 1; l < 4; l++)
                if (head[l] < head[best]) best = l;
            u64 v = head[best];
            ptr[best]++;
            head[best] = (ptr[best] < KK) ? L[best * KK + ptr[best]] : ~0ull;

            out[base + k]                   = funkey((u32)(v >> 32));
            out[(size_t)TOT + base + k]     = (float)((int)(u32)(v & 0xffffffffu)) + goff;
            out[2 * (size_t)TOT + base + k] = srcv;
        }
    }
}

extern "C" void kernel_launch(void* const* d_in, const int* in_sizes, int n_in,
                              void* d_out, int out_size) {
    const float* h = (const float*)d_in[0];
    (void)in_sizes; (void)n_in; (void)out_size;

    x2_kernel<<<(NS * NP + 255) / 256, 256>>>(h);

    dim3 grid(NP / QT, NS);   // 32 x 16 = 512 blocks
    knn_kernel<<<grid, BLK>>>(h, (float*)d_out);
}